// round 4
// baseline (speedup 1.0000x reference)
#include <cuda_runtime.h>
#include <math.h>

#define BB 2
#define TT 1024
#define DD 1024
#define HH 16
#define HKV 8
#define HD 64
#define NL 3
#define MAXKV 3072
#define EPSI 1e-5f
#define NEGINF (-1e30f)

// ---------------- device scratch (static; no allocation) ----------------
__device__ float g_Q[BB*TT*DD];             // roped Q per layer
__device__ float g_K[BB*MAXKV*HKV*HD];      // rotated K cache
__device__ float g_V[BB*MAXKV*HKV*HD];      // V cache
__device__ float g_O[BB*TT*DD];             // attention out per layer
__device__ float g_acc[BB*TT*DD];           // accumulated branch sum
__device__ float g_y[BB*TT*DD];             // pre-outproj activations
__device__ float g_lw[NL];

// ---------------- lambda weights -------------------------------------
__global__ void compute_lw(const float* __restrict__ lam) {
    if (threadIdx.x == 0) {
        float s0 = 1.f/(1.f+expf(-lam[0]));
        float s1 = 1.f/(1.f+expf(-lam[1]));
        float s2 = 1.f/(1.f+expf(-lam[2]));
        float mean = (s0+s1+s2)*(1.f/3.f);
        float d0 = s0-mean, d1 = s1-mean, d2 = s2-mean;
        float var = (d0*d0+d1*d1+d2*d2)*(1.f/3.f);
        float r = rsqrtf(var + EPSI);
        g_lw[0] = d0*r; g_lw[1] = d1*r; g_lw[2] = d2*r;
    }
}

// ---------------- GEMM core: C(128x128) = A(128xK) * W(128xK)^T --------
// A, W row-major with leading dim DD=1024. 256 threads, 8x8 per thread.
__device__ __forceinline__ void outer_acc(float4 c[4], float4 a, float4 b) {
    c[0].x += a.x*b.x; c[0].y += a.x*b.y; c[0].z += a.x*b.z; c[0].w += a.x*b.w;
    c[1].x += a.y*b.x; c[1].y += a.y*b.y; c[1].z += a.y*b.z; c[1].w += a.y*b.w;
    c[2].x += a.z*b.x; c[2].y += a.z*b.y; c[2].z += a.z*b.z; c[2].w += a.z*b.w;
    c[3].x += a.w*b.x; c[3].y += a.w*b.y; c[3].z += a.w*b.z; c[3].w += a.w*b.w;
}

__device__ __forceinline__ void gemm_main(const float* __restrict__ A,
                                          const float* __restrict__ W,
                                          float* As, float* Bs,
                                          float4 co[2][2][4],
                                          int tid, int tx, int ty) {
    for (int kt = 0; kt < 64; kt++) {
        #pragma unroll
        for (int j = 0; j < 2; j++) {
            int f = tid + j*256;
            int r = f >> 2, c4 = f & 3;
            float4 av = *(const float4*)(A + (size_t)r*DD + kt*16 + c4*4);
            float4 bv = *(const float4*)(W + (size_t)r*DD + kt*16 + c4*4);
            int c0 = c4*4;
            As[(c0+0)*132 + r] = av.x; As[(c0+1)*132 + r] = av.y;
            As[(c0+2)*132 + r] = av.z; As[(c0+3)*132 + r] = av.w;
            Bs[(c0+0)*132 + r] = bv.x; Bs[(c0+1)*132 + r] = bv.y;
            Bs[(c0+2)*132 + r] = bv.z; Bs[(c0+3)*132 + r] = bv.w;
        }
        __syncthreads();
        #pragma unroll
        for (int kk = 0; kk < 16; kk++) {
            const float* Ar = As + kk*132;
            const float* Br = Bs + kk*132;
            float4 a0 = *(const float4*)(Ar + ty*4);
            float4 a1 = *(const float4*)(Ar + 64 + ty*4);
            float4 b0 = *(const float4*)(Br + tx*4);
            float4 b1 = *(const float4*)(Br + 64 + tx*4);
            outer_acc(co[0][0], a0, b0);
            outer_acc(co[0][1], a0, b1);
            outer_acc(co[1][0], a1, b0);
            outer_acc(co[1][1], a1, b1);
        }
        __syncthreads();
    }
}

// ---------------- fused QKV projection -------------------------------
// grid (16 row-tiles, 16 virtual col-tiles). cols: [0,1024) Q, [1024,1536) K, [1536,2048) V
__global__ __launch_bounds__(256) void qkv_gemm(const float* __restrict__ x,
                                                const float* __restrict__ qw,
                                                const float* __restrict__ kw,
                                                const float* __restrict__ vw,
                                                int layer) {
    __shared__ float As[16*132];
    __shared__ float Bs[16*132];
    int tid = threadIdx.x, tx = tid & 15, ty = tid >> 4;
    int bm = blockIdx.x, bn = blockIdx.y;
    const float* A = x + (size_t)bm*128*DD;
    const float* W;
    int mode, lc0;
    if (bn < 8)       { W = qw + (size_t)layer*DD*DD     + (size_t)bn*128*DD;      mode = 0; lc0 = bn*128; }
    else if (bn < 12) { W = kw + (size_t)layer*(DD/2)*DD + (size_t)(bn-8)*128*DD;  mode = 1; lc0 = (bn-8)*128; }
    else              { W = vw + (size_t)layer*(DD/2)*DD + (size_t)(bn-12)*128*DD; mode = 2; lc0 = (bn-12)*128; }

    float4 co[2][2][4];
    #pragma unroll
    for (int a = 0; a < 2; a++)
        #pragma unroll
        for (int bq = 0; bq < 2; bq++)
            #pragma unroll
            for (int i = 0; i < 4; i++) co[a][bq][i] = make_float4(0.f,0.f,0.f,0.f);

    gemm_main(A, W, As, Bs, co, tid, tx, ty);

    #pragma unroll
    for (int im = 0; im < 2; im++)
        #pragma unroll
        for (int i = 0; i < 4; i++) {
            int m = bm*128 + im*64 + ty*4 + i;
            int b = m >> 10, t = m & 1023;
            #pragma unroll
            for (int jn = 0; jn < 2; jn++) {
                int lc = lc0 + jn*64 + tx*4;
                float4 v = co[im][jn][i];
                if (mode == 0) {
                    *(float4*)(g_Q + (size_t)m*DD + lc) = v;
                } else {
                    float* dst = (mode == 1) ? g_K : g_V;
                    size_t row = (size_t)(b*MAXKV + layer*TT + t);
                    *(float4*)(dst + row*(HKV*HD) + lc) = v;
                }
            }
        }
}

// ---------------- output projection ----------------------------------
__global__ __launch_bounds__(256) void out_gemm(const float* __restrict__ ow,
                                                float* __restrict__ out) {
    __shared__ float As[16*132];
    __shared__ float Bs[16*132];
    int tid = threadIdx.x, tx = tid & 15, ty = tid >> 4;
    int bm = blockIdx.x, bn = blockIdx.y;
    const float* A = g_y + (size_t)bm*128*DD;
    const float* W = ow + (size_t)bn*128*DD;

    float4 co[2][2][4];
    #pragma unroll
    for (int a = 0; a < 2; a++)
        #pragma unroll
        for (int bq = 0; bq < 2; bq++)
            #pragma unroll
            for (int i = 0; i < 4; i++) co[a][bq][i] = make_float4(0.f,0.f,0.f,0.f);

    gemm_main(A, W, As, Bs, co, tid, tx, ty);

    #pragma unroll
    for (int im = 0; im < 2; im++)
        #pragma unroll
        for (int i = 0; i < 4; i++) {
            int m = bm*128 + im*64 + ty*4 + i;
            #pragma unroll
            for (int jn = 0; jn < 2; jn++) {
                int col = bn*128 + jn*64 + tx*4;
                *(float4*)(out + (size_t)m*DD + col) = co[im][jn][i];
            }
        }
}

// ---------------- fused RoPE (Q + K) ----------------------------------
// Flat index space: first B*T*H*32 threads rotate Q halves,
// next B*T*HKV*32 threads rotate K halves (at absolute position layer*T + t).
#define NQROPE (BB*TT*HH*32)
#define NKROPE (BB*TT*HKV*32)
__global__ void rope_qk(const float* __restrict__ cosT, const float* __restrict__ sinT, int layer) {
    int idx = blockIdx.x * blockDim.x + threadIdx.x;
    if (idx < NQROPE) {
        int d = idx & 31;
        int h = (idx >> 5) & 15;
        int t = (idx >> 9) & 1023;
        int b = idx >> 19;
        size_t base = ((size_t)(b*TT + t))*DD + h*HD + d;
        float x1 = g_Q[base], x2 = g_Q[base + 32];
        float c = cosT[t*32 + d], s = sinT[t*32 + d];
        g_Q[base]      = x1*c - x2*s;
        g_Q[base + 32] = x2*c + x1*s;
    } else {
        int k = idx - NQROPE;
        int d  = k & 31;
        int kh = (k >> 5) & 7;
        int t  = (k >> 8) & 1023;
        int b  = k >> 18;
        int p  = layer*TT + t;
        size_t base = ((size_t)(b*MAXKV + p))*(HKV*HD) + kh*HD + d;
        float x1 = g_K[base], x2 = g_K[base + 32];
        float c = cosT[p*32 + d], s = sinT[p*32 + d];
        g_K[base]      = x1*c - x2*s;
        g_K[base + 32] = x2*c + x1*s;
    }
}

// ---------------- flash attention ------------------------------------
// grid (qtile=16, h=16, b=2), 256 threads. 64x64 Q-tile, 64-wide KV tiles.
// Smem 48KB: Qs,Ks,Vs (float4[1024] each), XOR-swizzled. P reuses Ks.
__device__ __forceinline__ void fma4s(float4& c, float s, float4 v) {
    c.x += s*v.x; c.y += s*v.y; c.z += s*v.z; c.w += s*v.w;
}

__global__ __launch_bounds__(256) void attn_kernel(int layer) {
    __shared__ float4 Qs[1024];
    __shared__ float4 Ks[1024];
    __shared__ float4 Vs[1024];
    int tid = threadIdx.x, tx = tid & 15, ty = tid >> 4;
    int qt = blockIdx.x, h = blockIdx.y, b = blockIdx.z;
    int t0 = qt * 64, kh = h >> 1;
    const float scale = 0.125f;  // HD^-0.5

    // load Q tile (scale folded in)
    #pragma unroll
    for (int j = 0; j < 4; j++) {
        int f = tid + j*256;
        int qr = f >> 4, d4 = f & 15;
        float4 v = *(const float4*)(g_Q + ((size_t)(b*TT + t0 + qr))*DD + h*HD + d4*4);
        v.x *= scale; v.y *= scale; v.z *= scale; v.w *= scale;
        Qs[qr*16 + (d4 ^ ((qr >> 2) & 7))] = v;
    }

    float4 oacc[4];
    float mrow[4], lrow[4];
    #pragma unroll
    for (int qi = 0; qi < 4; qi++) {
        oacc[qi] = make_float4(0.f,0.f,0.f,0.f);
        mrow[qi] = NEGINF; lrow[qi] = 0.f;
    }

    int ntiles = qt + layer*16 + 1;
    int swq = ty & 7, swk = tx & 7;

    for (int jt = 0; jt < ntiles; jt++) {
        __syncthreads();
        #pragma unroll
        for (int j = 0; j < 4; j++) {
            int f = tid + j*256;
            int kr = f >> 4, d4 = f & 15;
            size_t gro = ((size_t)(b*MAXKV + jt*64 + kr))*(HKV*HD) + kh*HD + d4*4;
            int sidx = kr*16 + (d4 ^ ((kr >> 2) & 7));
            Ks[sidx] = *(const float4*)(g_K + gro);
            Vs[sidx] = *(const float4*)(g_V + gro);
        }
        __syncthreads();

        // S = Qs * Ks^T  (per-thread 4x4)
        float s[4][4];
        #pragma unroll
        for (int qi = 0; qi < 4; qi++)
            #pragma unroll
            for (int kj = 0; kj < 4; kj++) s[qi][kj] = 0.f;

        #pragma unroll
        for (int d4 = 0; d4 < 16; d4++) {
            float4 a0 = Qs[(ty*4+0)*16 + (d4 ^ swq)];
            float4 a1 = Qs[(ty*4+1)*16 + (d4 ^ swq)];
            float4 a2 = Qs[(ty*4+2)*16 + (d4 ^ swq)];
            float4 a3 = Qs[(ty*4+3)*16 + (d4 ^ swq)];
            float4 k0 = Ks[(tx*4+0)*16 + (d4 ^ swk)];
            float4 k1 = Ks[(tx*4+1)*16 + (d4 ^ swk)];
            float4 k2 = Ks[(tx*4+2)*16 + (d4 ^ swk)];
            float4 k3 = Ks[(tx*4+3)*16 + (d4 ^ swk)];
            s[0][0] += a0.x*k0.x + a0.y*k0.y + a0.z*k0.z + a0.w*k0.w;
            s[0][1] += a0.x*k1.x + a0.y*k1.y + a0.z*k1.z + a0.w*k1.w;
            s[0][2] += a0.x*k2.x + a0.y*k2.y + a0.z*k2.z + a0.w*k2.w;
            s[0][3] += a0.x*k3.x + a0.y*k3.y + a0.z*k3.z + a0.w*k3.w;
            s[1][0] += a1.x*k0.x + a1.y*k0.y + a1.z*k0.z + a1.w*k0.w;
            s[1][1] += a1.x*k1.x + a1.y*k1.y + a1.z*k1.z + a1.w*k1.w;
            s[1][2] += a1.x*k2.x + a1.y*k2.y + a1.z*k2.z + a1.w*k2.w;
            s[1][3] += a1.x*k3.x + a1.y*k3.y + a1.z*k3.z + a1.w*k3.w;
            s[2][0] += a2.x*k0.x + a2.y*k0.y + a2.z*k0.z + a2.w*k0.w;
            s[2][1] += a2.x*k1.x + a2.y*k1.y + a2.z*k1.z + a2.w*k1.w;
            s[2][2] += a2.x*k2.x + a2.y*k2.y + a2.z*k2.z + a2.w*k2.w;
            s[2][3] += a2.x*k3.x + a2.y*k3.y + a2.z*k3.z + a2.w*k3.w;
            s[3][0] += a3.x*k0.x + a3.y*k0.y + a3.z*k0.z + a3.w*k0.w;
            s[3][1] += a3.x*k1.x + a3.y*k1.y + a3.z*k1.z + a3.w*k1.w;
            s[3][2] += a3.x*k2.x + a3.y*k2.y + a3.z*k2.z + a3.w*k2.w;
            s[3][3] += a3.x*k3.x + a3.y*k3.y + a3.z*k3.z + a3.w*k3.w;
        }

        // mask + online softmax
        #pragma unroll
        for (int qi = 0; qi < 4; qi++) {
            int lim = t0 + ty*4 + qi + layer*TT;
            int kg = jt*64 + tx*4;
            if (kg + 0 > lim) s[qi][0] = NEGINF;
            if (kg + 1 > lim) s[qi][1] = NEGINF;
            if (kg + 2 > lim) s[qi][2] = NEGINF;
            if (kg + 3 > lim) s[qi][3] = NEGINF;
            float mx = fmaxf(fmaxf(s[qi][0], s[qi][1]), fmaxf(s[qi][2], s[qi][3]));
            mx = fmaxf(mx, __shfl_xor_sync(0xffffffffu, mx, 1));
            mx = fmaxf(mx, __shfl_xor_sync(0xffffffffu, mx, 2));
            mx = fmaxf(mx, __shfl_xor_sync(0xffffffffu, mx, 4));
            mx = fmaxf(mx, __shfl_xor_sync(0xffffffffu, mx, 8));
            float mnew = fmaxf(mrow[qi], mx);
            float corr = __expf(mrow[qi] - mnew);
            mrow[qi] = mnew;
            float rs = 0.f;
            #pragma unroll
            for (int kj = 0; kj < 4; kj++) {
                s[qi][kj] = __expf(s[qi][kj] - mnew);
                rs += s[qi][kj];
            }
            rs += __shfl_xor_sync(0xffffffffu, rs, 1);
            rs += __shfl_xor_sync(0xffffffffu, rs, 2);
            rs += __shfl_xor_sync(0xffffffffu, rs, 4);
            rs += __shfl_xor_sync(0xffffffffu, rs, 8);
            lrow[qi] = lrow[qi]*corr + rs;
            oacc[qi].x *= corr; oacc[qi].y *= corr; oacc[qi].z *= corr; oacc[qi].w *= corr;
        }

        __syncthreads();  // done reading Ks; reuse it for P
        #pragma unroll
        for (int qi = 0; qi < 4; qi++)
            Ks[(ty*4+qi)*16 + (tx ^ swq)] = make_float4(s[qi][0], s[qi][1], s[qi][2], s[qi][3]);
        __syncthreads();

        // O += P * V
        #pragma unroll
        for (int k4 = 0; k4 < 16; k4++) {
            float4 p0 = Ks[(ty*4+0)*16 + (k4 ^ swq)];
            float4 p1 = Ks[(ty*4+1)*16 + (k4 ^ swq)];
            float4 p2 = Ks[(ty*4+2)*16 + (k4 ^ swq)];
            float4 p3 = Ks[(ty*4+3)*16 + (k4 ^ swq)];
            int swv = k4 & 7;
            float4 v0 = Vs[(k4*4+0)*16 + (tx ^ swv)];
            float4 v1 = Vs[(k4*4+1)*16 + (tx ^ swv)];
            float4 v2 = Vs[(k4*4+2)*16 + (tx ^ swv)];
            float4 v3 = Vs[(k4*4+3)*16 + (tx ^ swv)];
            fma4s(oacc[0], p0.x, v0); fma4s(oacc[0], p0.y, v1); fma4s(oacc[0], p0.z, v2); fma4s(oacc[0], p0.w, v3);
            fma4s(oacc[1], p1.x, v0); fma4s(oacc[1], p1.y, v1); fma4s(oacc[1], p1.z, v2); fma4s(oacc[1], p1.w, v3);
            fma4s(oacc[2], p2.x, v0); fma4s(oacc[2], p2.y, v1); fma4s(oacc[2], p2.z, v2); fma4s(oacc[2], p2.w, v3);
            fma4s(oacc[3], p3.x, v0); fma4s(oacc[3], p3.y, v1); fma4s(oacc[3], p3.z, v2); fma4s(oacc[3], p3.w, v3);
        }
    }

    #pragma unroll
    for (int qi = 0; qi < 4; qi++) {
        float inv = 1.0f / lrow[qi];
        float4 v = oacc[qi];
        v.x *= inv; v.y *= inv; v.z *= inv; v.w *= inv;
        *(float4*)(g_O + ((size_t)(b*TT + t0 + ty*4 + qi))*DD + h*HD + tx*4) = v;
    }
}

// ---------------- row reductions -------------------------------------
__device__ __forceinline__ float block_reduce_sum(float v, float* red, int tid) {
    v += __shfl_xor_sync(0xffffffffu, v, 16);
    v += __shfl_xor_sync(0xffffffffu, v, 8);
    v += __shfl_xor_sync(0xffffffffu, v, 4);
    v += __shfl_xor_sync(0xffffffffu, v, 2);
    v += __shfl_xor_sync(0xffffffffu, v, 1);
    if ((tid & 31) == 0) red[tid >> 5] = v;
    __syncthreads();
    if (tid < 32) {
        float w = (tid < 8) ? red[tid] : 0.f;
        w += __shfl_xor_sync(0xffffffffu, w, 4);
        w += __shfl_xor_sync(0xffffffffu, w, 2);
        w += __shfl_xor_sync(0xffffffffu, w, 1);
        if (tid == 0) red[0] = w;
    }
    __syncthreads();
    return red[0];
}

__global__ __launch_bounds__(256) void rmsnorm_acc(const float* __restrict__ lnw, int layer) {
    __shared__ float red[8];
    int row = blockIdx.x, tid = threadIdx.x;
    float4 o = *(const float4*)(g_O + (size_t)row*DD + tid*4);
    float ss = o.x*o.x + o.y*o.y + o.z*o.z + o.w*o.w;
    float total = block_reduce_sum(ss, red, tid);
    float r = rsqrtf(total * (1.0f/DD) + EPSI) * g_lw[layer];
    float4 w = *(const float4*)(lnw + (size_t)layer*DD + tid*4);
    float4 res = make_float4(o.x*r*w.x, o.y*r*w.y, o.z*r*w.z, o.w*r*w.w);
    float* ap = g_acc + (size_t)row*DD + tid*4;
    if (layer == 0) {
        *(float4*)ap = res;
    } else {
        float4 a = *(const float4*)ap;
        a.x += res.x; a.y += res.y; a.z += res.z; a.w += res.w;
        *(float4*)ap = a;
    }
}

__global__ __launch_bounds__(256) void final_norm(const float* __restrict__ x,
                                                  const float* __restrict__ flnw,
                                                  const float* __restrict__ alpha) {
    __shared__ float red[8];
    int row = blockIdx.x, tid = threadIdx.x;
    float al = alpha[0];
    float4 a = *(const float4*)(g_acc + (size_t)row*DD + tid*4);
    float4 xv = *(const float4*)(x + (size_t)row*DD + tid*4);
    float4 v = make_float4(a.x + al*xv.x, a.y + al*xv.y, a.z + al*xv.z, a.w + al*xv.w);
    float ss = v.x*v.x + v.y*v.y + v.z*v.z + v.w*v.w;
    float total = block_reduce_sum(ss, red, tid);
    float r = rsqrtf(total * (1.0f/DD) + EPSI);
    float4 w = *(const float4*)(flnw + tid*4);
    float4 res = make_float4(v.x*r*w.x, v.y*r*w.y, v.z*r*w.z, v.w*r*w.w);
    *(float4*)(g_y + (size_t)row*DD + tid*4) = res;
}

// ---------------- launch ---------------------------------------------
extern "C" void kernel_launch(void* const* d_in, const int* in_sizes, int n_in,
                              void* d_out, int out_size) {
    const float* x    = (const float*)d_in[0];
    const float* cosT = (const float*)d_in[1];
    const float* sinT = (const float*)d_in[2];
    const float* qw   = (const float*)d_in[3];
    const float* kw   = (const float*)d_in[4];
    const float* vw   = (const float*)d_in[5];
    const float* lnw  = (const float*)d_in[6];
    const float* lam  = (const float*)d_in[7];
    const float* ow   = (const float*)d_in[8];
    const float* flnw = (const float*)d_in[9];
    const float* alpha= (const float*)d_in[10];
    float* out = (float*)d_out;

    compute_lw<<<1, 32>>>(lam);

    for (int layer = 0; layer < NL; layer++) {
        qkv_gemm<<<dim3(16, 16), 256>>>(x, qw, kw, vw, layer);
        rope_qk<<<(NQROPE + NKROPE)/256, 256>>>(cosT, sinT, layer);
        attn_kernel<<<dim3(16, HH, BB), 256>>>(layer);
        rmsnorm_acc<<<BB*TT, 256>>>(lnw, layer);
    }

    final_norm<<<BB*TT, 256>>>(x, flnw, alpha);
    out_gemm<<<dim3(16, 8), 256>>>(ow, out);
}

// round 6
// speedup vs baseline: 1.2769x; 1.2769x over previous
#include <cuda_runtime.h>
#include <math.h>
#include <cstdint>

#define BB 2
#define TT 1024
#define DD 1024
#define HH 16
#define HKV 8
#define HD 64
#define NL 3
#define MAXKV 3072
#define EPSI 1e-5f
#define NEGINF (-1e30f)

// ---------------- device scratch (static; no allocation) ----------------
__device__ float g_Q[BB*TT*DD];             // roped Q per layer
__device__ float g_K[BB*MAXKV*HKV*HD];      // rotated K cache
__device__ float g_V[BB*MAXKV*HKV*HD];      // V cache
__device__ float g_O[BB*TT*DD];             // attention out per layer
__device__ float g_acc[BB*TT*DD];           // accumulated branch sum
__device__ float g_y[BB*TT*DD];             // pre-outproj activations
__device__ float g_lw[NL];

// ================= tf32 mma.sync helpers ==============================
__device__ __forceinline__ uint32_t f2tf32(float x) {
    uint32_t u;
    asm("cvt.rna.tf32.f32 %0, %1;" : "=r"(u) : "f"(x));
    return u;
}

__device__ __forceinline__ void mma_16n8k8(float c[4], const uint32_t a[4], const uint32_t b[2]) {
    asm volatile("mma.sync.aligned.m16n8k8.row.col.f32.tf32.tf32.f32 "
        "{%0,%1,%2,%3}, {%4,%5,%6,%7}, {%8,%9}, {%0,%1,%2,%3};"
        : "+f"(c[0]), "+f"(c[1]), "+f"(c[2]), "+f"(c[3])
        : "r"(a[0]), "r"(a[1]), "r"(a[2]), "r"(a[3]), "r"(b[0]), "r"(b[1]));
}

#define SSTRIDE 36   // padded smem row stride in words: (4r + c) % 32 all-distinct -> conflict-free frags

// C(128x128) = A(128x1024) * W(128x1024)^T, tf32 MMA, fp32 accum.
// 256 threads = 8 warps; warp tile 64x32 = 4x4 m16n8k8; K staged 32/iter.
__device__ __forceinline__ void tf32_mainloop(const float* __restrict__ A,
                                              const float* __restrict__ W,
                                              uint32_t* As, uint32_t* Ws,
                                              float c[4][4][4],
                                              int tid, int lane, int wm0, int wn0) {
    for (int kt = 0; kt < 32; kt++) {
        #pragma unroll
        for (int j = 0; j < 4; j++) {
            int f = tid + j*256;          // 0..1023
            int r = f >> 3, cc = (f & 7)*4;
            float4 av = *(const float4*)(A + (size_t)r*DD + kt*32 + cc);
            float4 wv = *(const float4*)(W + (size_t)r*DD + kt*32 + cc);
            uint32_t* pa = As + r*SSTRIDE + cc;
            pa[0] = f2tf32(av.x); pa[1] = f2tf32(av.y); pa[2] = f2tf32(av.z); pa[3] = f2tf32(av.w);
            uint32_t* pw = Ws + r*SSTRIDE + cc;
            pw[0] = f2tf32(wv.x); pw[1] = f2tf32(wv.y); pw[2] = f2tf32(wv.z); pw[3] = f2tf32(wv.w);
        }
        __syncthreads();
        #pragma unroll
        for (int ks = 0; ks < 4; ks++) {
            int k0 = ks*8;
            uint32_t a[4][4], b[4][2];
            #pragma unroll
            for (int mi = 0; mi < 4; mi++) {
                int row = wm0 + mi*16 + (lane >> 2);
                const uint32_t* p = As + row*SSTRIDE + k0 + (lane & 3);
                a[mi][0] = p[0];
                a[mi][1] = p[8*SSTRIDE];
                a[mi][2] = p[4];
                a[mi][3] = p[8*SSTRIDE + 4];
            }
            #pragma unroll
            for (int ni = 0; ni < 4; ni++) {
                int coln = wn0 + ni*8 + (lane >> 2);
                const uint32_t* p = Ws + coln*SSTRIDE + k0 + (lane & 3);
                b[ni][0] = p[0];
                b[ni][1] = p[4];
            }
            #pragma unroll
            for (int mi = 0; mi < 4; mi++)
                #pragma unroll
                for (int ni = 0; ni < 4; ni++)
                    mma_16n8k8(c[mi][ni], a[mi], b[ni]);
        }
        __syncthreads();
    }
}

// ---------------- fused QKV projection (tf32 mma) ---------------------
// grid (16, 16): cols [0,1024) Q, [1024,1536) K, [1536,2048) V
__global__ __launch_bounds__(256) void qkv_gemm_tc(const float* __restrict__ x,
                                                   const float* __restrict__ qw,
                                                   const float* __restrict__ kw,
                                                   const float* __restrict__ vw,
                                                   int layer) {
    __shared__ uint32_t As[128*SSTRIDE];
    __shared__ uint32_t Ws[128*SSTRIDE];
    int tid = threadIdx.x, lane = tid & 31, wid = tid >> 5;
    int wm0 = (wid >> 2)*64, wn0 = (wid & 3)*32;
    int bm = blockIdx.x, bn = blockIdx.y;
    const float* A = x + (size_t)bm*128*DD;
    const float* W;
    int mode, lc0;
    if (bn < 8)       { W = qw + (size_t)layer*DD*DD     + (size_t)bn*128*DD;      mode = 0; lc0 = bn*128; }
    else if (bn < 12) { W = kw + (size_t)layer*(DD/2)*DD + (size_t)(bn-8)*128*DD;  mode = 1; lc0 = (bn-8)*128; }
    else              { W = vw + (size_t)layer*(DD/2)*DD + (size_t)(bn-12)*128*DD; mode = 2; lc0 = (bn-12)*128; }

    float c[4][4][4];
    #pragma unroll
    for (int mi = 0; mi < 4; mi++)
        #pragma unroll
        for (int ni = 0; ni < 4; ni++)
            #pragma unroll
            for (int q = 0; q < 4; q++) c[mi][ni][q] = 0.f;

    tf32_mainloop(A, W, As, Ws, c, tid, lane, wm0, wn0);

    float* kvbase = (mode == 1) ? g_K : g_V;
    #pragma unroll
    for (int mi = 0; mi < 4; mi++) {
        #pragma unroll
        for (int half = 0; half < 2; half++) {
            int mrow = bm*128 + wm0 + mi*16 + half*8 + (lane >> 2);
            float* dst;
            if (mode == 0) {
                dst = g_Q + (size_t)mrow*DD + lc0;
            } else {
                int b = mrow >> 10, t = mrow & 1023;
                dst = kvbase + ((size_t)(b*MAXKV + layer*TT + t))*(HKV*HD) + lc0;
            }
            #pragma unroll
            for (int ni = 0; ni < 4; ni++) {
                int col = wn0 + ni*8 + (lane & 3)*2;
                float2 v = half ? make_float2(c[mi][ni][2], c[mi][ni][3])
                                : make_float2(c[mi][ni][0], c[mi][ni][1]);
                *(float2*)(dst + col) = v;
            }
        }
    }
}

// ---------------- output projection (tf32 mma) ------------------------
__global__ __launch_bounds__(256) void out_gemm_tc(const float* __restrict__ ow,
                                                   float* __restrict__ out) {
    __shared__ uint32_t As[128*SSTRIDE];
    __shared__ uint32_t Ws[128*SSTRIDE];
    int tid = threadIdx.x, lane = tid & 31, wid = tid >> 5;
    int wm0 = (wid >> 2)*64, wn0 = (wid & 3)*32;
    int bm = blockIdx.x, bn = blockIdx.y;
    const float* A = g_y + (size_t)bm*128*DD;
    const float* W = ow + (size_t)bn*128*DD;

    float c[4][4][4];
    #pragma unroll
    for (int mi = 0; mi < 4; mi++)
        #pragma unroll
        for (int ni = 0; ni < 4; ni++)
            #pragma unroll
            for (int q = 0; q < 4; q++) c[mi][ni][q] = 0.f;

    tf32_mainloop(A, W, As, Ws, c, tid, lane, wm0, wn0);

    #pragma unroll
    for (int mi = 0; mi < 4; mi++) {
        #pragma unroll
        for (int half = 0; half < 2; half++) {
            int mrow = bm*128 + wm0 + mi*16 + half*8 + (lane >> 2);
            float* dst = out + (size_t)mrow*DD + bn*128;
            #pragma unroll
            for (int ni = 0; ni < 4; ni++) {
                int col = wn0 + ni*8 + (lane & 3)*2;
                float2 v = half ? make_float2(c[mi][ni][2], c[mi][ni][3])
                                : make_float2(c[mi][ni][0], c[mi][ni][1]);
                *(float2*)(dst + col) = v;
            }
        }
    }
}

// ---------------- lambda weights -------------------------------------
__global__ void compute_lw(const float* __restrict__ lam) {
    if (threadIdx.x == 0) {
        float s0 = 1.f/(1.f+expf(-lam[0]));
        float s1 = 1.f/(1.f+expf(-lam[1]));
        float s2 = 1.f/(1.f+expf(-lam[2]));
        float mean = (s0+s1+s2)*(1.f/3.f);
        float d0 = s0-mean, d1 = s1-mean, d2 = s2-mean;
        float var = (d0*d0+d1*d1+d2*d2)*(1.f/3.f);
        float r = rsqrtf(var + EPSI);
        g_lw[0] = d0*r; g_lw[1] = d1*r; g_lw[2] = d2*r;
    }
}

// ---------------- fused RoPE (Q + K) ----------------------------------
#define NQROPE (BB*TT*HH*32)
#define NKROPE (BB*TT*HKV*32)
__global__ void rope_qk(const float* __restrict__ cosT, const float* __restrict__ sinT, int layer) {
    int idx = blockIdx.x * blockDim.x + threadIdx.x;
    if (idx < NQROPE) {
        int d = idx & 31;
        int h = (idx >> 5) & 15;
        int t = (idx >> 9) & 1023;
        int b = idx >> 19;
        size_t base = ((size_t)(b*TT + t))*DD + h*HD + d;
        float x1 = g_Q[base], x2 = g_Q[base + 32];
        float c = cosT[t*32 + d], s = sinT[t*32 + d];
        g_Q[base]      = x1*c - x2*s;
        g_Q[base + 32] = x2*c + x1*s;
    } else {
        int k = idx - NQROPE;
        int d  = k & 31;
        int kh = (k >> 5) & 7;
        int t  = (k >> 8) & 1023;
        int b  = k >> 18;
        int p  = layer*TT + t;
        size_t base = ((size_t)(b*MAXKV + p))*(HKV*HD) + kh*HD + d;
        float x1 = g_K[base], x2 = g_K[base + 32];
        float c = cosT[p*32 + d], s = sinT[p*32 + d];
        g_K[base]      = x1*c - x2*s;
        g_K[base + 32] = x2*c + x1*s;
    }
}

// ---------------- flash attention (SIMT) ------------------------------
__device__ __forceinline__ void fma4s(float4& c, float s, float4 v) {
    c.x += s*v.x; c.y += s*v.y; c.z += s*v.z; c.w += s*v.w;
}

__global__ __launch_bounds__(256) void attn_kernel(int layer) {
    __shared__ float4 Qs[1024];
    __shared__ float4 Ks[1024];
    __shared__ float4 Vs[1024];
    int tid = threadIdx.x, tx = tid & 15, ty = tid >> 4;
    int qt = blockIdx.x, h = blockIdx.y, b = blockIdx.z;
    int t0 = qt * 64, kh = h >> 1;
    const float scale = 0.125f;

    #pragma unroll
    for (int j = 0; j < 4; j++) {
        int f = tid + j*256;
        int qr = f >> 4, d4 = f & 15;
        float4 v = *(const float4*)(g_Q + ((size_t)(b*TT + t0 + qr))*DD + h*HD + d4*4);
        v.x *= scale; v.y *= scale; v.z *= scale; v.w *= scale;
        Qs[qr*16 + (d4 ^ ((qr >> 2) & 7))] = v;
    }

    float4 oacc[4];
    float mrow[4], lrow[4];
    #pragma unroll
    for (int qi = 0; qi < 4; qi++) {
        oacc[qi] = make_float4(0.f,0.f,0.f,0.f);
        mrow[qi] = NEGINF; lrow[qi] = 0.f;
    }

    int ntiles = qt + layer*16 + 1;
    int swq = ty & 7, swk = tx & 7;

    for (int jt = 0; jt < ntiles; jt++) {
        __syncthreads();
        #pragma unroll
        for (int j = 0; j < 4; j++) {
            int f = tid + j*256;
            int kr = f >> 4, d4 = f & 15;
            size_t gro = ((size_t)(b*MAXKV + jt*64 + kr))*(HKV*HD) + kh*HD + d4*4;
            int sidx = kr*16 + (d4 ^ ((kr >> 2) & 7));
            Ks[sidx] = *(const float4*)(g_K + gro);
            Vs[sidx] = *(const float4*)(g_V + gro);
        }
        __syncthreads();

        float s[4][4];
        #pragma unroll
        for (int qi = 0; qi < 4; qi++)
            #pragma unroll
            for (int kj = 0; kj < 4; kj++) s[qi][kj] = 0.f;

        #pragma unroll
        for (int d4 = 0; d4 < 16; d4++) {
            float4 a0 = Qs[(ty*4+0)*16 + (d4 ^ swq)];
            float4 a1 = Qs[(ty*4+1)*16 + (d4 ^ swq)];
            float4 a2 = Qs[(ty*4+2)*16 + (d4 ^ swq)];
            float4 a3 = Qs[(ty*4+3)*16 + (d4 ^ swq)];
            float4 k0 = Ks[(tx*4+0)*16 + (d4 ^ swk)];
            float4 k1 = Ks[(tx*4+1)*16 + (d4 ^ swk)];
            float4 k2 = Ks[(tx*4+2)*16 + (d4 ^ swk)];
            float4 k3 = Ks[(tx*4+3)*16 + (d4 ^ swk)];
            s[0][0] += a0.x*k0.x + a0.y*k0.y + a0.z*k0.z + a0.w*k0.w;
            s[0][1] += a0.x*k1.x + a0.y*k1.y + a0.z*k1.z + a0.w*k1.w;
            s[0][2] += a0.x*k2.x + a0.y*k2.y + a0.z*k2.z + a0.w*k2.w;
            s[0][3] += a0.x*k3.x + a0.y*k3.y + a0.z*k3.z + a0.w*k3.w;
            s[1][0] += a1.x*k0.x + a1.y*k0.y + a1.z*k0.z + a1.w*k0.w;
            s[1][1] += a1.x*k1.x + a1.y*k1.y + a1.z*k1.z + a1.w*k1.w;
            s[1][2] += a1.x*k2.x + a1.y*k2.y + a1.z*k2.z + a1.w*k2.w;
            s[1][3] += a1.x*k3.x + a1.y*k3.y + a1.z*k3.z + a1.w*k3.w;
            s[2][0] += a2.x*k0.x + a2.y*k0.y + a2.z*k0.z + a2.w*k0.w;
            s[2][1] += a2.x*k1.x + a2.y*k1.y + a2.z*k1.z + a2.w*k1.w;
            s[2][2] += a2.x*k2.x + a2.y*k2.y + a2.z*k2.z + a2.w*k2.w;
            s[2][3] += a2.x*k3.x + a2.y*k3.y + a2.z*k3.z + a2.w*k3.w;
            s[3][0] += a3.x*k0.x + a3.y*k0.y + a3.z*k0.z + a3.w*k0.w;
            s[3][1] += a3.x*k1.x + a3.y*k1.y + a3.z*k1.z + a3.w*k1.w;
            s[3][2] += a3.x*k2.x + a3.y*k2.y + a3.z*k2.z + a3.w*k2.w;
            s[3][3] += a3.x*k3.x + a3.y*k3.y + a3.z*k3.z + a3.w*k3.w;
        }

        #pragma unroll
        for (int qi = 0; qi < 4; qi++) {
            int lim = t0 + ty*4 + qi + layer*TT;
            int kg = jt*64 + tx*4;
            if (kg + 0 > lim) s[qi][0] = NEGINF;
            if (kg + 1 > lim) s[qi][1] = NEGINF;
            if (kg + 2 > lim) s[qi][2] = NEGINF;
            if (kg + 3 > lim) s[qi][3] = NEGINF;
            float mx = fmaxf(fmaxf(s[qi][0], s[qi][1]), fmaxf(s[qi][2], s[qi][3]));
            mx = fmaxf(mx, __shfl_xor_sync(0xffffffffu, mx, 1));
            mx = fmaxf(mx, __shfl_xor_sync(0xffffffffu, mx, 2));
            mx = fmaxf(mx, __shfl_xor_sync(0xffffffffu, mx, 4));
            mx = fmaxf(mx, __shfl_xor_sync(0xffffffffu, mx, 8));
            float mnew = fmaxf(mrow[qi], mx);
            float corr = __expf(mrow[qi] - mnew);
            mrow[qi] = mnew;
            float rs = 0.f;
            #pragma unroll
            for (int kj = 0; kj < 4; kj++) {
                s[qi][kj] = __expf(s[qi][kj] - mnew);
                rs += s[qi][kj];
            }
            rs += __shfl_xor_sync(0xffffffffu, rs, 1);
            rs += __shfl_xor_sync(0xffffffffu, rs, 2);
            rs += __shfl_xor_sync(0xffffffffu, rs, 4);
            rs += __shfl_xor_sync(0xffffffffu, rs, 8);
            lrow[qi] = lrow[qi]*corr + rs;
            oacc[qi].x *= corr; oacc[qi].y *= corr; oacc[qi].z *= corr; oacc[qi].w *= corr;
        }

        __syncthreads();
        #pragma unroll
        for (int qi = 0; qi < 4; qi++)
            Ks[(ty*4+qi)*16 + (tx ^ swq)] = make_float4(s[qi][0], s[qi][1], s[qi][2], s[qi][3]);
        __syncthreads();

        #pragma unroll
        for (int k4 = 0; k4 < 16; k4++) {
            float4 p0 = Ks[(ty*4+0)*16 + (k4 ^ swq)];
            float4 p1 = Ks[(ty*4+1)*16 + (k4 ^ swq)];
            float4 p2 = Ks[(ty*4+2)*16 + (k4 ^ swq)];
            float4 p3 = Ks[(ty*4+3)*16 + (k4 ^ swq)];
            int swv = k4 & 7;
            float4 v0 = Vs[(k4*4+0)*16 + (tx ^ swv)];
            float4 v1 = Vs[(k4*4+1)*16 + (tx ^ swv)];
            float4 v2 = Vs[(k4*4+2)*16 + (tx ^ swv)];
            float4 v3 = Vs[(k4*4+3)*16 + (tx ^ swv)];
            fma4s(oacc[0], p0.x, v0); fma4s(oacc[0], p0.y, v1); fma4s(oacc[0], p0.z, v2); fma4s(oacc[0], p0.w, v3);
            fma4s(oacc[1], p1.x, v0); fma4s(oacc[1], p1.y, v1); fma4s(oacc[1], p1.z, v2); fma4s(oacc[1], p1.w, v3);
            fma4s(oacc[2], p2.x, v0); fma4s(oacc[2], p2.y, v1); fma4s(oacc[2], p2.z, v2); fma4s(oacc[2], p2.w, v3);
            fma4s(oacc[3], p3.x, v0); fma4s(oacc[3], p3.y, v1); fma4s(oacc[3], p3.z, v2); fma4s(oacc[3], p3.w, v3);
        }
    }

    #pragma unroll
    for (int qi = 0; qi < 4; qi++) {
        float inv = 1.0f / lrow[qi];
        float4 v = oacc[qi];
        v.x *= inv; v.y *= inv; v.z *= inv; v.w *= inv;
        *(float4*)(g_O + ((size_t)(b*TT + t0 + ty*4 + qi))*DD + h*HD + tx*4) = v;
    }
}

// ---------------- row reductions -------------------------------------
__device__ __forceinline__ float block_reduce_sum(float v, float* red, int tid) {
    v += __shfl_xor_sync(0xffffffffu, v, 16);
    v += __shfl_xor_sync(0xffffffffu, v, 8);
    v += __shfl_xor_sync(0xffffffffu, v, 4);
    v += __shfl_xor_sync(0xffffffffu, v, 2);
    v += __shfl_xor_sync(0xffffffffu, v, 1);
    if ((tid & 31) == 0) red[tid >> 5] = v;
    __syncthreads();
    if (tid < 32) {
        float w = (tid < 8) ? red[tid] : 0.f;
        w += __shfl_xor_sync(0xffffffffu, w, 4);
        w += __shfl_xor_sync(0xffffffffu, w, 2);
        w += __shfl_xor_sync(0xffffffffu, w, 1);
        if (tid == 0) red[0] = w;
    }
    __syncthreads();
    return red[0];
}

__global__ __launch_bounds__(256) void rmsnorm_acc(const float* __restrict__ lnw, int layer) {
    __shared__ float red[8];
    int row = blockIdx.x, tid = threadIdx.x;
    float4 o = *(const float4*)(g_O + (size_t)row*DD + tid*4);
    float ss = o.x*o.x + o.y*o.y + o.z*o.z + o.w*o.w;
    float total = block_reduce_sum(ss, red, tid);
    float r = rsqrtf(total * (1.0f/DD) + EPSI) * g_lw[layer];
    float4 w = *(const float4*)(lnw + (size_t)layer*DD + tid*4);
    float4 res = make_float4(o.x*r*w.x, o.y*r*w.y, o.z*r*w.z, o.w*r*w.w);
    float* ap = g_acc + (size_t)row*DD + tid*4;
    if (layer == 0) {
        *(float4*)ap = res;
    } else {
        float4 a = *(const float4*)ap;
        a.x += res.x; a.y += res.y; a.z += res.z; a.w += res.w;
        *(float4*)ap = a;
    }
}

__global__ __launch_bounds__(256) void final_norm(const float* __restrict__ x,
                                                  const float* __restrict__ flnw,
                                                  const float* __restrict__ alpha) {
    __shared__ float red[8];
    int row = blockIdx.x, tid = threadIdx.x;
    float al = alpha[0];
    float4 a = *(const float4*)(g_acc + (size_t)row*DD + tid*4);
    float4 xv = *(const float4*)(x + (size_t)row*DD + tid*4);
    float4 v = make_float4(a.x + al*xv.x, a.y + al*xv.y, a.z + al*xv.z, a.w + al*xv.w);
    float ss = v.x*v.x + v.y*v.y + v.z*v.z + v.w*v.w;
    float total = block_reduce_sum(ss, red, tid);
    float r = rsqrtf(total * (1.0f/DD) + EPSI);
    float4 w = *(const float4*)(flnw + tid*4);
    float4 res = make_float4(v.x*r*w.x, v.y*r*w.y, v.z*r*w.z, v.w*r*w.w);
    *(float4*)(g_y + (size_t)row*DD + tid*4) = res;
}

// ---------------- launch ---------------------------------------------
extern "C" void kernel_launch(void* const* d_in, const int* in_sizes, int n_in,
                              void* d_out, int out_size) {
    const float* x    = (const float*)d_in[0];
    const float* cosT = (const float*)d_in[1];
    const float* sinT = (const float*)d_in[2];
    const float* qw   = (const float*)d_in[3];
    const float* kw   = (const float*)d_in[4];
    const float* vw   = (const float*)d_in[5];
    const float* lnw  = (const float*)d_in[6];
    const float* lam  = (const float*)d_in[7];
    const float* ow   = (const float*)d_in[8];
    const float* flnw = (const float*)d_in[9];
    const float* alpha= (const float*)d_in[10];
    float* out = (float*)d_out;

    compute_lw<<<1, 32>>>(lam);

    for (int layer = 0; layer < NL; layer++) {
        qkv_gemm_tc<<<dim3(16, 16), 256>>>(x, qw, kw, vw, layer);
        rope_qk<<<(NQROPE + NKROPE)/256, 256>>>(cosT, sinT, layer);
        attn_kernel<<<dim3(16, HH, BB), 256>>>(layer);
        rmsnorm_acc<<<BB*TT, 256>>>(lnw, layer);
    }

    final_norm<<<BB*TT, 256>>>(x, flnw, alpha);
    out_gemm_tc<<<dim3(16, 8), 256>>>(ow, out);
}